// round 16
// baseline (speedup 1.0000x reference)
#include <cuda_runtime.h>
#include <cuda_bf16.h>

// PyramidROIAlign: output [B,N,7,7,256] f32, levels p2..p5 (256/128/64/32), NHWC.
// R16 (final tune of the winning R15 shape):
//  - warp per (roi,py,px) sample; 8 batched LDG.128 gathers; 2x STG.128 .cs
//  - setup: no IDIV (subtract loop), fused meta LDG.64, single-MUFU level select
//  - block=512 (halves block count -> less dispatch overhead), exact grid,
//    no bounds guard (98000 warps divisible by 16 warps/block).
// Kernel sits at the L1tex line-service floor (~40 lines/sample @ ~2 cyc/line).

#define POOLX 7
#define C4N 64   // 256 ch / 4

__global__ __launch_bounds__(512, 4) void roi_align_warp_kernel(
    const float* __restrict__ boxes,   // [M,4]  (y1,x1,y2,x2)
    const float* __restrict__ meta,    // [B,93]
    const float* __restrict__ p2,
    const float* __restrict__ p3,
    const float* __restrict__ p4,
    const float* __restrict__ p5,
    float* __restrict__ out,
    int totalWarps, int N)
{
    int gw   = (blockIdx.x * blockDim.x + threadIdx.x) >> 5;  // warp id = sample id
    int lane = threadIdx.x & 31;
    if (gw >= totalWarps) return;   // compiled but never taken for exact grids

    int pos = gw % 49;
    int roi = gw / 49;
    int py  = pos / POOLX;
    int px  = pos - py * POOLX;

    // b = roi / N without IDIV (B tiny, warp-uniform)
    int b = 0, r = roi;
    while (r >= N) { r -= N; b++; }

    // ---- per-warp uniform setup ----
    float4 bx = __ldg(((const float4*)boxes) + roi);
    float y1 = bx.x, x1 = bx.y, y2 = bx.z, x2 = bx.w;
    float h = y2 - y1, w = x2 - x1;

    float2 hw = __ldg((const float2*)(meta + 4));   // meta[4], meta[5]
    float area = hw.x * hw.y;

    // log2(scale*sqrt(area)/224) = 0.5*(log2(max(h*w,1e-12)) + log2(area)) - log2(224)
    float rl = 0.5f * (__log2f(fmaxf(h * w, 1e-12f)) + __log2f(area)) - 7.8073549221f;
    int lvl = 4 + (int)rintf(rl);
    lvl = min(max(lvl, 2), 5);

    const float* fmap;
    int H;
    if      (lvl == 2) { fmap = p2; H = 256; }
    else if (lvl == 3) { fmap = p3; H = 128; }
    else if (lvl == 4) { fmap = p4; H = 64;  }
    else               { fmap = p5; H = 32;  }
    const int W = H;

    float ty = (float)py * (1.0f / 6.0f);
    float tx = (float)px * (1.0f / 6.0f);
    float ys = (y1 + ty * h) * (float)(H - 1);
    float xs = (x1 + tx * w) * (float)(W - 1);

    float fy = floorf(ys), fx = floorf(xs);
    float ly = ys - fy,    lx = xs - fx;

    int y0  = min(max((int)fy,     0), H - 1);
    int y1i = min(max((int)fy + 1, 0), H - 1);
    int x0  = min(max((int)fx,     0), W - 1);
    int x1i = min(max((int)fx + 1, 0), W - 1);

    float w11 = ly * lx;
    float w01 = lx - w11;            // lx*(1-ly)
    float w10 = ly - w11;            // ly*(1-lx)
    float w00 = 1.0f - lx - w10;     // (1-lx)*(1-ly)

    const float4* f4 = (const float4*)fmap;
    int rowT = (b * H + y0 ) * W;
    int rowB = (b * H + y1i) * W;
    int cA = lane, cB = lane + 32;
    int o00 = (rowT + x0 ) * C4N + cA;
    int o01 = (rowT + x1i) * C4N + cA;
    int o10 = (rowB + x0 ) * C4N + cA;
    int o11 = (rowB + x1i) * C4N + cA;

    // ---- hot path: 8x LDG.128 batched, FFMAs, 2x STG.128 .cs ----
    float4 a00 = __ldg(f4 + o00);
    float4 a01 = __ldg(f4 + o01);
    float4 a10 = __ldg(f4 + o10);
    float4 a11 = __ldg(f4 + o11);
    float4 b00 = __ldg(f4 + o00 + 32);
    float4 b01 = __ldg(f4 + o01 + 32);
    float4 b10 = __ldg(f4 + o10 + 32);
    float4 b11 = __ldg(f4 + o11 + 32);

    float4 ra, rb;
    ra.x = a00.x*w00 + a01.x*w01 + a10.x*w10 + a11.x*w11;
    ra.y = a00.y*w00 + a01.y*w01 + a10.y*w10 + a11.y*w11;
    ra.z = a00.z*w00 + a01.z*w01 + a10.z*w10 + a11.z*w11;
    ra.w = a00.w*w00 + a01.w*w01 + a10.w*w10 + a11.w*w11;
    rb.x = b00.x*w00 + b01.x*w01 + b10.x*w10 + b11.x*w11;
    rb.y = b00.y*w00 + b01.y*w01 + b10.y*w10 + b11.y*w11;
    rb.z = b00.z*w00 + b01.z*w01 + b10.z*w10 + b11.z*w11;
    rb.w = b00.w*w00 + b01.w*w01 + b10.w*w10 + b11.w*w11;

    float4* o4 = (float4*)out + gw * C4N;
    __stcs(o4 + cA, ra);
    __stcs(o4 + cB, rb);
}

extern "C" void kernel_launch(void* const* d_in, const int* in_sizes, int n_in,
                              void* d_out, int out_size) {
    const float* boxes = (const float*)d_in[0];
    const float* meta  = (const float*)d_in[1];
    const float* p2    = (const float*)d_in[2];
    const float* p3    = (const float*)d_in[3];
    const float* p4    = (const float*)d_in[4];
    const float* p5    = (const float*)d_in[5];
    float* out = (float*)d_out;

    int B = in_sizes[1] / 93;              // image_meta [B,93]
    if (B <= 0) B = 2;
    int N = in_sizes[0] / (4 * B);         // boxes [B,N,4]
    int M = B * N;
    int totalWarps = M * 49;               // one warp per (roi, py, px)

    int threads = 512;                      // 16 warps per block
    int warpsPerBlock = threads / 32;
    int blocks = (totalWarps + warpsPerBlock - 1) / warpsPerBlock;
    roi_align_warp_kernel<<<blocks, threads>>>(boxes, meta, p2, p3, p4, p5, out,
                                               totalWarps, N);
}

// round 17
// speedup vs baseline: 1.0420x; 1.0420x over previous
#include <cuda_runtime.h>
#include <cuda_bf16.h>

// PyramidROIAlign: output [B,N,7,7,256] f32, levels p2..p5 (256/128/64/32), NHWC.
// FINAL (R15 configuration — best measured kernel time, 30.98us):
//  - one WARP per (roi,py,px) sample; lane handles float4 channels lane & lane+32
//  - 8 front-batched LDG.128 gathers (4 bilinear corners x 2 halves)
//  - 2x STG.128 .cs streaming stores (keep the 100MB output out of L2's way)
//  - setup trimmed: no IDIV (subtract loop), fused meta LDG.64,
//    level select via 0.5*(log2(h*w)+log2(area)) - log2(224), round-half-even
//  - block=256, __launch_bounds__(256,8) -> 32 regs, occ ~83%
// Kernel sits at the sm_103a L1tex line-service floor
// (~40 cache lines/sample @ ~2 cyc/line across 148 SMs ~= 31us).

#define POOLX 7
#define C4N 64   // 256 ch / 4

__global__ __launch_bounds__(256, 8) void roi_align_warp_kernel(
    const float* __restrict__ boxes,   // [M,4]  (y1,x1,y2,x2)
    const float* __restrict__ meta,    // [B,93]
    const float* __restrict__ p2,
    const float* __restrict__ p3,
    const float* __restrict__ p4,
    const float* __restrict__ p5,
    float* __restrict__ out,
    int totalWarps, int N)
{
    int gw   = (blockIdx.x * blockDim.x + threadIdx.x) >> 5;  // warp id = sample id
    int lane = threadIdx.x & 31;
    if (gw >= totalWarps) return;

    int pos = gw % 49;
    int roi = gw / 49;
    int py  = pos / POOLX;
    int px  = pos - py * POOLX;

    // b = roi / N without runtime IDIV (B tiny; warp-uniform)
    int b = 0, r = roi;
    while (r >= N) { r -= N; b++; }

    // ---- per-warp uniform setup ----
    float4 bx = __ldg(((const float4*)boxes) + roi);
    float y1 = bx.x, x1 = bx.y, y2 = bx.z, x2 = bx.w;
    float h = y2 - y1, w = x2 - x1;

    float2 hw = __ldg((const float2*)(meta + 4));   // meta[4], meta[5]
    float area = hw.x * hw.y;

    // log2(scale*sqrt(area)/224) = 0.5*(log2(max(h*w,1e-12)) + log2(area)) - log2(224)
    float rl = 0.5f * (__log2f(fmaxf(h * w, 1e-12f)) + __log2f(area)) - 7.8073549221f;
    int lvl = 4 + (int)rintf(rl);
    lvl = min(max(lvl, 2), 5);

    const float* fmap;
    int H;
    if      (lvl == 2) { fmap = p2; H = 256; }
    else if (lvl == 3) { fmap = p3; H = 128; }
    else if (lvl == 4) { fmap = p4; H = 64;  }
    else               { fmap = p5; H = 32;  }
    const int W = H;

    float ty = (float)py * (1.0f / 6.0f);
    float tx = (float)px * (1.0f / 6.0f);
    float ys = (y1 + ty * h) * (float)(H - 1);
    float xs = (x1 + tx * w) * (float)(W - 1);

    float fy = floorf(ys), fx = floorf(xs);
    float ly = ys - fy,    lx = xs - fx;

    int y0  = min(max((int)fy,     0), H - 1);
    int y1i = min(max((int)fy + 1, 0), H - 1);
    int x0  = min(max((int)fx,     0), W - 1);
    int x1i = min(max((int)fx + 1, 0), W - 1);

    float w11 = ly * lx;
    float w01 = lx - w11;            // lx*(1-ly)
    float w10 = ly - w11;            // ly*(1-lx)
    float w00 = 1.0f - lx - w10;     // (1-lx)*(1-ly)

    const float4* f4 = (const float4*)fmap;
    int rowT = (b * H + y0 ) * W;
    int rowB = (b * H + y1i) * W;
    int cA = lane, cB = lane + 32;
    int o00 = (rowT + x0 ) * C4N + cA;
    int o01 = (rowT + x1i) * C4N + cA;
    int o10 = (rowB + x0 ) * C4N + cA;
    int o11 = (rowB + x1i) * C4N + cA;

    // ---- hot path: 8x LDG.128 batched, FFMAs, 2x STG.128 .cs ----
    float4 a00 = __ldg(f4 + o00);
    float4 a01 = __ldg(f4 + o01);
    float4 a10 = __ldg(f4 + o10);
    float4 a11 = __ldg(f4 + o11);
    float4 b00 = __ldg(f4 + o00 + 32);
    float4 b01 = __ldg(f4 + o01 + 32);
    float4 b10 = __ldg(f4 + o10 + 32);
    float4 b11 = __ldg(f4 + o11 + 32);

    float4 ra, rb;
    ra.x = a00.x*w00 + a01.x*w01 + a10.x*w10 + a11.x*w11;
    ra.y = a00.y*w00 + a01.y*w01 + a10.y*w10 + a11.y*w11;
    ra.z = a00.z*w00 + a01.z*w01 + a10.z*w10 + a11.z*w11;
    ra.w = a00.w*w00 + a01.w*w01 + a10.w*w10 + a11.w*w11;
    rb.x = b00.x*w00 + b01.x*w01 + b10.x*w10 + b11.x*w11;
    rb.y = b00.y*w00 + b01.y*w01 + b10.y*w10 + b11.y*w11;
    rb.z = b00.z*w00 + b01.z*w01 + b10.z*w10 + b11.z*w11;
    rb.w = b00.w*w00 + b01.w*w01 + b10.w*w10 + b11.w*w11;

    float4* o4 = (float4*)out + gw * C4N;
    __stcs(o4 + cA, ra);
    __stcs(o4 + cB, rb);
}

extern "C" void kernel_launch(void* const* d_in, const int* in_sizes, int n_in,
                              void* d_out, int out_size) {
    const float* boxes = (const float*)d_in[0];
    const float* meta  = (const float*)d_in[1];
    const float* p2    = (const float*)d_in[2];
    const float* p3    = (const float*)d_in[3];
    const float* p4    = (const float*)d_in[4];
    const float* p5    = (const float*)d_in[5];
    float* out = (float*)d_out;

    int B = in_sizes[1] / 93;              // image_meta [B,93]
    if (B <= 0) B = 2;
    int N = in_sizes[0] / (4 * B);         // boxes [B,N,4]
    int M = B * N;
    int totalWarps = M * 49;               // one warp per (roi, py, px)

    int threads = 256;                      // 8 warps per block
    int warpsPerBlock = threads / 32;
    int blocks = (totalWarps + warpsPerBlock - 1) / warpsPerBlock;
    roi_align_warp_kernel<<<blocks, threads>>>(boxes, meta, p2, p3, p4, p5, out,
                                               totalWarps, N);
}